// round 2
// baseline (speedup 1.0000x reference)
#include <cuda_runtime.h>
#include <math.h>

#define BB 4
#define CC 64
#define NN 4096
#define KK 256
#define PP 256

// Scratch (no allocs allowed) ------------------------------------------------
__device__ float g_ent[BB * NN];          // per-row entropy
__device__ int   g_sel[BB * KK];          // selected row indices (sorted)
__device__ float g_samp[BB * KK * CC];    // sampled = attn_k @ patches

// ---------------------------------------------------------------------------
// Pass 1: per-row softmax stats + entropy, streaming (flash-attention style).
// grid (32 itiles, B), 256 threads, 48 KB static smem.
// Thread (ty,tx) = (t/16, t%16); rows i = ty+16u (u<8), cols j = tx+16v (v<4).
// ---------------------------------------------------------------------------
__global__ void entropy_kernel(const float* __restrict__ L) {
    __shared__ float Xi[64 * 128];   // 32 KB, [c][ii]
    __shared__ float Xj[64 * 64];    // 16 KB, [c][jj]; reused as scratch after loop

    const int b  = blockIdx.y;
    const int i0 = blockIdx.x * 128;
    const int t  = threadIdx.x;
    const int tx = t & 15, ty = t >> 4;
    const float* Lb = L + (size_t)b * CC * NN;

    for (int idx = t; idx < 64 * 128; idx += 256) {
        int c = idx >> 7, ii = idx & 127;
        Xi[c * 128 + ii] = Lb[c * NN + i0 + ii];
    }

    float m[8], z[8], tt[8];
#pragma unroll
    for (int u = 0; u < 8; u++) { m[u] = -1e30f; z[u] = 0.f; tt[u] = 0.f; }

    for (int jt = 0; jt < 64; jt++) {
        __syncthreads();
        for (int idx = t; idx < 64 * 64; idx += 256) {
            int c = idx >> 6, jj = idx & 63;
            Xj[c * 64 + jj] = Lb[c * NN + jt * 64 + jj];
        }
        __syncthreads();

        float acc[8][4];
#pragma unroll
        for (int u = 0; u < 8; u++)
#pragma unroll
            for (int v = 0; v < 4; v++) acc[u][v] = 0.f;

#pragma unroll 4
        for (int c = 0; c < 64; c++) {
            float a[8], bb[4];
#pragma unroll
            for (int u = 0; u < 8; u++) a[u] = Xi[c * 128 + ty + 16 * u];
#pragma unroll
            for (int v = 0; v < 4; v++) bb[v] = Xj[c * 64 + tx + 16 * v];
#pragma unroll
            for (int u = 0; u < 8; u++)
#pragma unroll
                for (int v = 0; v < 4; v++) acc[u][v] += a[u] * bb[v];
        }

        // online (m, Z, T) update per row; T = sum s*e^s with s = score - m
#pragma unroll
        for (int u = 0; u < 8; u++) {
            float lm = acc[u][0];
#pragma unroll
            for (int v = 1; v < 4; v++) lm = fmaxf(lm, acc[u][v]);
            float nm = fmaxf(m[u], lm);
            float eo = __expf(m[u] - nm);
            float zn = z[u] * eo;
            float tn = (tt[u] + z[u] * (m[u] - nm)) * eo;
#pragma unroll
            for (int v = 0; v < 4; v++) {
                float s = acc[u][v] - nm;
                float e = __expf(s);
                zn += e;
                tn += s * e;
            }
            m[u] = nm; z[u] = zn; tt[u] = tn;
        }
    }

    // cross-thread (tx) merge per row using Xj as scratch, then
    // entropy = logZ - T/Z.
    float* rm  = Xj;           // [16][16]
    float* rz  = Xj + 256;
    float* rt2 = Xj + 512;
    for (int u = 0; u < 8; u++) {
        __syncthreads();
        rm[ty * 16 + tx] = m[u]; rz[ty * 16 + tx] = z[u]; rt2[ty * 16 + tx] = tt[u];
        __syncthreads();
        if (tx == 0) {
            float M = rm[ty * 16], Z = rz[ty * 16], T = rt2[ty * 16];
            for (int x = 1; x < 16; x++) {
                float mi = rm[ty * 16 + x], zi = rz[ty * 16 + x], ti = rt2[ty * 16 + x];
                float nm = fmaxf(M, mi);
                float ea = __expf(M - nm), eb = __expf(mi - nm);
                T = (T + Z * (M - nm)) * ea + (ti + zi * (mi - nm)) * eb;
                Z = Z * ea + zi * eb;
                M = nm;
            }
            g_ent[b * NN + i0 + ty + 16 * u] = logf(Z) - T / Z;
        }
    }
}

// ---------------------------------------------------------------------------
// Pass 2: per-batch bitonic sort of 4096 (entropy, index) pairs, ascending.
// Lexicographic tie-break on index == stable argsort. 4 blocks x 1024 thr.
// ---------------------------------------------------------------------------
__global__ void sort_kernel(float* __restrict__ out_idx) {
    __shared__ float key[NN];
    __shared__ int   val[NN];
    const int b = blockIdx.x, t = threadIdx.x;
    for (int i = t; i < NN; i += 1024) { key[i] = g_ent[b * NN + i]; val[i] = i; }
    __syncthreads();
    for (int k = 2; k <= NN; k <<= 1) {
        for (int j = k >> 1; j > 0; j >>= 1) {
            for (int i = t; i < NN; i += 1024) {
                int ixj = i ^ j;
                if (ixj > i) {
                    bool up = ((i & k) == 0);
                    float ka = key[i], kb = key[ixj];
                    int va = val[i], vb = val[ixj];
                    bool agtb = (ka > kb) || (ka == kb && va > vb);
                    if (agtb == up) {
                        key[i] = kb; key[ixj] = ka;
                        val[i] = vb; val[ixj] = va;
                    }
                }
            }
            __syncthreads();
        }
    }
    if (t < KK) {
        int v = val[t];
        g_sel[b * KK + t] = v;
        out_idx[b * KK + t] = (float)v;
    }
}

// ---------------------------------------------------------------------------
// Pass 3a: raw scores for the 256 selected rows -> attn output region.
// grid (16 ktiles, B), 256 threads. Thread: row r = t%16, col group cg = t/16,
// cols jj = cg + 16v. Staged through shared for coalesced stores.
// ---------------------------------------------------------------------------
__global__ void scores_kernel(const float* __restrict__ L, float* __restrict__ attn) {
    __shared__ float Xi[64 * 16];
    __shared__ float Xj[64 * 128];
    __shared__ float S[16 * 132];
    const int b  = blockIdx.y;
    const int k0 = blockIdx.x * 16;
    const int t  = threadIdx.x;
    const int r = t & 15, cg = t >> 4;
    const float* Lb = L + (size_t)b * CC * NN;

    for (int idx = t; idx < 64 * 16; idx += 256) {
        int c = idx >> 4, rr = idx & 15;
        int col = g_sel[b * KK + k0 + rr];
        Xi[c * 16 + rr] = Lb[c * NN + col];
    }

    for (int jt = 0; jt < 32; jt++) {
        __syncthreads();
        for (int idx = t; idx < 64 * 128; idx += 256) {
            int c = idx >> 7, jj = idx & 127;
            Xj[c * 128 + jj] = Lb[c * NN + jt * 128 + jj];
        }
        __syncthreads();
        float acc[8];
#pragma unroll
        for (int v = 0; v < 8; v++) acc[v] = 0.f;
#pragma unroll 4
        for (int c = 0; c < 64; c++) {
            float a = Xi[c * 16 + r];
#pragma unroll
            for (int v = 0; v < 8; v++) acc[v] += a * Xj[c * 128 + cg + 16 * v];
        }
#pragma unroll
        for (int v = 0; v < 8; v++) S[r * 132 + cg + 16 * v] = acc[v];
        __syncthreads();
        for (int idx = t; idx < 2048; idx += 256) {
            int rr = idx >> 7, jj = idx & 127;
            attn[((size_t)b * KK + k0 + rr) * NN + jt * 128 + jj] = S[rr * 132 + jj];
        }
    }
}

// ---------------------------------------------------------------------------
// Pass 3b: softmax each selected row in place. 1024 blocks x 256 threads.
// ---------------------------------------------------------------------------
__global__ void softmax_kernel(float* __restrict__ attn) {
    const int row = blockIdx.x;
    float* p = attn + (size_t)row * NN;
    const int t = threadIdx.x;
    __shared__ float red[256];

    float v[16];
    float lm = -1e30f;
#pragma unroll
    for (int i = 0; i < 16; i++) { v[i] = p[t + 256 * i]; lm = fmaxf(lm, v[i]); }
    red[t] = lm; __syncthreads();
    for (int s = 128; s > 0; s >>= 1) { if (t < s) red[t] = fmaxf(red[t], red[t + s]); __syncthreads(); }
    float M = red[0];
    __syncthreads();
    float ls = 0.f;
#pragma unroll
    for (int i = 0; i < 16; i++) { v[i] = __expf(v[i] - M); ls += v[i]; }
    red[t] = ls; __syncthreads();
    for (int s = 128; s > 0; s >>= 1) { if (t < s) red[t] += red[t + s]; __syncthreads(); }
    float inv = 1.f / red[0];
#pragma unroll
    for (int i = 0; i < 16; i++) p[t + 256 * i] = v[i] * inv;
}

// ---------------------------------------------------------------------------
// Pass 3c: sampled[b,k,c] = sum_j attn[b,k,j] * X[b,c,j].
// grid (8 ktiles, B), 256 threads. Thread: c = t%64, k = (t/64) + 4u.
// ---------------------------------------------------------------------------
__global__ void sampled_kernel(const float* __restrict__ L, const float* __restrict__ attn) {
    __shared__ float XT[64 * 65];   // [jj][c], padded
    __shared__ float Pt[32 * 64];   // [k][jj]
    const int b  = blockIdx.y;
    const int k0 = blockIdx.x * 32;
    const int t  = threadIdx.x;
    const int tc = t & 63, tk = t >> 6;  // tk in 0..3
    const float* Lb = L + (size_t)b * CC * NN;

    float acc[8];
#pragma unroll
    for (int u = 0; u < 8; u++) acc[u] = 0.f;

    for (int jt = 0; jt < 64; jt++) {
        __syncthreads();
        for (int idx = t; idx < 64 * 64; idx += 256) {
            int c = idx >> 6, jj = idx & 63;
            XT[jj * 65 + c] = Lb[c * NN + jt * 64 + jj];
        }
        for (int idx = t; idx < 32 * 64; idx += 256) {
            int kk = idx >> 6, jj = idx & 63;
            Pt[kk * 64 + jj] = attn[((size_t)b * KK + k0 + kk) * NN + jt * 64 + jj];
        }
        __syncthreads();
#pragma unroll 4
        for (int jj = 0; jj < 64; jj++) {
            float x = XT[jj * 65 + tc];
#pragma unroll
            for (int u = 0; u < 8; u++) acc[u] += Pt[(tk + 4 * u) * 64 + jj] * x;
        }
    }
#pragma unroll
    for (int u = 0; u < 8; u++)
        g_samp[((size_t)b * KK + k0 + tk + 4 * u) * CC + tc] = acc[u];
}

// ---------------------------------------------------------------------------
// Pass 4: MLP + L2 normalize. 1024 blocks (one per (b,k)) x 256 threads.
// ---------------------------------------------------------------------------
__global__ void mlp_kernel(const float* __restrict__ w1, const float* __restrict__ b1,
                           const float* __restrict__ w2, const float* __restrict__ b2,
                           float* __restrict__ emb) {
    const int row = blockIdx.x;
    const int t = threadIdx.x;
    __shared__ float s[CC];
    __shared__ float h[PP];
    __shared__ float red[256];

    if (t < CC) s[t] = g_samp[(size_t)row * CC + t];
    __syncthreads();

    float acc = b1[t];
#pragma unroll 8
    for (int c = 0; c < CC; c++) acc += s[c] * w1[c * PP + t];
    h[t] = fmaxf(acc, 0.f);
    __syncthreads();

    float o = b2[t];
#pragma unroll 8
    for (int p2 = 0; p2 < PP; p2++) o += h[p2] * w2[p2 * PP + t];

    red[t] = o * o;
    __syncthreads();
    for (int sd = 128; sd > 0; sd >>= 1) { if (t < sd) red[t] += red[t + sd]; __syncthreads(); }
    float nrm = sqrtf(red[0]);
    float denom = fmaxf(nrm, 1e-12f);
    emb[(size_t)row * PP + t] = o / denom;
}

// ---------------------------------------------------------------------------
extern "C" void kernel_launch(void* const* d_in, const int* in_sizes, int n_in,
                              void* d_out, int out_size) {
    const float* L  = (const float*)d_in[0];
    const float* w1 = (const float*)d_in[1];
    const float* b1 = (const float*)d_in[2];
    const float* w2 = (const float*)d_in[3];
    const float* b2 = (const float*)d_in[4];

    float* out  = (float*)d_out;
    float* emb  = out;                                   // [B,K,P]
    float* attn = out + (size_t)BB * KK * PP;            // [B,K,N]
    float* oidx = attn + (size_t)BB * KK * NN;           // [B,K]

    entropy_kernel<<<dim3(32, BB), 256>>>(L);
    sort_kernel<<<BB, 1024>>>(oidx);
    scores_kernel<<<dim3(16, BB), 256>>>(L, attn);
    softmax_kernel<<<BB * KK, 256>>>(attn);
    sampled_kernel<<<dim3(8, BB), 256>>>(L, attn);
    mlp_kernel<<<BB * KK, 256>>>(w1, b1, w2, b2, emb);
}

// round 3
// speedup vs baseline: 1.9885x; 1.9885x over previous
#include <cuda_runtime.h>
#include <math.h>

#define BB 4
#define CC 64
#define NN 4096
#define KK 256
#define PP 256

// Scratch (no allocs allowed) ------------------------------------------------
__device__ float g_pm[2][BB * NN];        // partial row max (per j-half)
__device__ float g_pz[2][BB * NN];        // partial Z
__device__ float g_pt[2][BB * NN];        // partial T = sum s*e^s
__device__ int   g_sel[BB * KK];          // selected row indices (sorted)
__device__ float g_samp4[4][BB * KK * CC];// j-quarter partials of sampled

// ---------------------------------------------------------------------------
// Pass 1: streaming softmax stats (m, Z, T) per row over one j-half.
// grid (32 itiles, 2 jhalves, B), 256 threads, 48 KB smem, 2 blocks/SM.
// Thread (ty,tx): rows i = i0 + ty*8 + u (u<8), cols j = jbase + jt*64 + tx*4 + v.
// ---------------------------------------------------------------------------
__global__ void __launch_bounds__(256, 2)
entropy_kernel(const float* __restrict__ L) {
    __shared__ __align__(16) float Xi[64 * 128];  // 32 KB [c][ii]
    __shared__ __align__(16) float Xj[64 * 64];   // 16 KB [c][jj]; scratch later

    const int b  = blockIdx.z;
    const int jh = blockIdx.y;
    const int i0 = blockIdx.x * 128;
    const int t  = threadIdx.x;
    const int tx = t & 15, ty = t >> 4;
    const float* Lb = L + (size_t)b * CC * NN;
    const int jbase = jh * 2048;

    for (int idx = t; idx < 2048; idx += 256) {          // 64*128/4 float4s
        int c = idx >> 5, q = idx & 31;
        ((float4*)Xi)[c * 32 + q] = ((const float4*)(Lb + (size_t)c * NN + i0))[q];
    }

    float m[8], z[8], tt[8];
#pragma unroll
    for (int u = 0; u < 8; u++) { m[u] = -1e30f; z[u] = 0.f; tt[u] = 0.f; }

    for (int jt = 0; jt < 32; jt++) {
        __syncthreads();
        for (int idx = t; idx < 1024; idx += 256) {      // 64*64/4
            int c = idx >> 4, q = idx & 15;
            ((float4*)Xj)[c * 16 + q] =
                ((const float4*)(Lb + (size_t)c * NN + jbase + jt * 64))[q];
        }
        __syncthreads();

        float acc[8][4];
#pragma unroll
        for (int u = 0; u < 8; u++)
#pragma unroll
            for (int v = 0; v < 4; v++) acc[u][v] = 0.f;

#pragma unroll 8
        for (int c = 0; c < 64; c++) {
            float4 a0 = *(const float4*)&Xi[c * 128 + ty * 8];
            float4 a1 = *(const float4*)&Xi[c * 128 + ty * 8 + 4];
            float4 bv = *(const float4*)&Xj[c * 64 + tx * 4];
            float a[8] = {a0.x, a0.y, a0.z, a0.w, a1.x, a1.y, a1.z, a1.w};
            float bbv[4] = {bv.x, bv.y, bv.z, bv.w};
#pragma unroll
            for (int u = 0; u < 8; u++)
#pragma unroll
                for (int v = 0; v < 4; v++) acc[u][v] += a[u] * bbv[v];
        }

        // online (m, Z, T) update per row
#pragma unroll
        for (int u = 0; u < 8; u++) {
            float lm = fmaxf(fmaxf(acc[u][0], acc[u][1]), fmaxf(acc[u][2], acc[u][3]));
            float nm = fmaxf(m[u], lm);
            float eo = __expf(m[u] - nm);
            float zn = z[u] * eo;
            float tn = (tt[u] + z[u] * (m[u] - nm)) * eo;
#pragma unroll
            for (int v = 0; v < 4; v++) {
                float s = acc[u][v] - nm;
                float e = __expf(s);
                zn += e;
                tn += s * e;
            }
            m[u] = nm; z[u] = zn; tt[u] = tn;
        }
    }

    // cross-thread (tx) merge per row using Xj as scratch; write partials.
    float* rm  = Xj;
    float* rz  = Xj + 256;
    float* rt2 = Xj + 512;
    for (int u = 0; u < 8; u++) {
        __syncthreads();
        rm[ty * 16 + tx] = m[u]; rz[ty * 16 + tx] = z[u]; rt2[ty * 16 + tx] = tt[u];
        __syncthreads();
        if (tx == 0) {
            float M = rm[ty * 16], Z = rz[ty * 16], T = rt2[ty * 16];
            for (int x = 1; x < 16; x++) {
                float mi = rm[ty * 16 + x], zi = rz[ty * 16 + x], ti = rt2[ty * 16 + x];
                float nm = fmaxf(M, mi);
                float ea = __expf(M - nm), eb = __expf(mi - nm);
                T = (T + Z * (M - nm)) * ea + (ti + zi * (mi - nm)) * eb;
                Z = Z * ea + zi * eb;
                M = nm;
            }
            int row = b * NN + i0 + ty * 8 + u;
            g_pm[jh][row] = M; g_pz[jh][row] = Z; g_pt[jh][row] = T;
        }
    }
}

// ---------------------------------------------------------------------------
// Pass 2: merge j-half stats -> entropy, then per-batch bitonic argsort
// (stable via (key, index) lexicographic compare). 4 blocks x 1024 threads.
// ---------------------------------------------------------------------------
__global__ void sort_kernel(float* __restrict__ out_idx) {
    __shared__ float key[NN];
    __shared__ int   val[NN];
    const int b = blockIdx.x, t = threadIdx.x;
    for (int i = t; i < NN; i += 1024) {
        int row = b * NN + i;
        float m0 = g_pm[0][row], z0 = g_pz[0][row], t0 = g_pt[0][row];
        float m1 = g_pm[1][row], z1 = g_pz[1][row], t1 = g_pt[1][row];
        float nm = fmaxf(m0, m1);
        float e0 = __expf(m0 - nm), e1 = __expf(m1 - nm);
        float Z = z0 * e0 + z1 * e1;
        float T = (t0 + z0 * (m0 - nm)) * e0 + (t1 + z1 * (m1 - nm)) * e1;
        key[i] = logf(Z) - T / Z;
        val[i] = i;
    }
    __syncthreads();
    for (int k = 2; k <= NN; k <<= 1) {
        for (int j = k >> 1; j > 0; j >>= 1) {
            for (int i = t; i < NN; i += 1024) {
                int ixj = i ^ j;
                if (ixj > i) {
                    bool up = ((i & k) == 0);
                    float ka = key[i], kb = key[ixj];
                    int va = val[i], vb = val[ixj];
                    bool agtb = (ka > kb) || (ka == kb && va > vb);
                    if (agtb == up) {
                        key[i] = kb; key[ixj] = ka;
                        val[i] = vb; val[ixj] = va;
                    }
                }
            }
            __syncthreads();
        }
    }
    if (t < KK) {
        int v = val[t];
        g_sel[b * KK + t] = v;
        out_idx[b * KK + t] = (float)v;
    }
}

// ---------------------------------------------------------------------------
// Pass 3a: raw scores for selected rows -> attn region.
// grid (16 ktiles, 2 jhalves, B), 256 threads. r = t%16 row, cg = t/16 owns
// 8 cols (2 float4s). Direct vectorized stores.
// ---------------------------------------------------------------------------
__global__ void scores_kernel(const float* __restrict__ L, float* __restrict__ attn) {
    __shared__ float Xi[64 * 16];
    __shared__ __align__(16) float Xj[64 * 128];
    const int b  = blockIdx.z;
    const int k0 = blockIdx.x * 16;
    const int jbase = blockIdx.y * 2048;
    const int t  = threadIdx.x;
    const int r = t & 15, cg = t >> 4;
    const float* Lb = L + (size_t)b * CC * NN;

    for (int idx = t; idx < 64 * 16; idx += 256) {
        int c = idx >> 4, rr = idx & 15;
        int col = g_sel[b * KK + k0 + rr];
        Xi[c * 16 + rr] = Lb[(size_t)c * NN + col];
    }

    for (int jt = 0; jt < 16; jt++) {
        __syncthreads();
        for (int idx = t; idx < 2048; idx += 256) {   // 64*128/4
            int c = idx >> 5, q = idx & 31;
            ((float4*)Xj)[c * 32 + q] =
                ((const float4*)(Lb + (size_t)c * NN + jbase + jt * 128))[q];
        }
        __syncthreads();
        float acc[8];
#pragma unroll
        for (int v = 0; v < 8; v++) acc[v] = 0.f;
#pragma unroll 8
        for (int c = 0; c < 64; c++) {
            float a = Xi[c * 16 + r];
            float4 b0 = *(const float4*)&Xj[c * 128 + cg * 8];
            float4 b1 = *(const float4*)&Xj[c * 128 + cg * 8 + 4];
            acc[0] += a * b0.x; acc[1] += a * b0.y; acc[2] += a * b0.z; acc[3] += a * b0.w;
            acc[4] += a * b1.x; acc[5] += a * b1.y; acc[6] += a * b1.z; acc[7] += a * b1.w;
        }
        float* dst = attn + ((size_t)b * KK + k0 + r) * NN + jbase + jt * 128 + cg * 8;
        *(float4*)dst       = make_float4(acc[0], acc[1], acc[2], acc[3]);
        *(float4*)(dst + 4) = make_float4(acc[4], acc[5], acc[6], acc[7]);
    }
}

// ---------------------------------------------------------------------------
// Pass 3b: softmax each selected row in place. 1024 blocks x 256 threads.
// ---------------------------------------------------------------------------
__global__ void softmax_kernel(float* __restrict__ attn) {
    const int row = blockIdx.x;
    float* p = attn + (size_t)row * NN;
    const int t = threadIdx.x;
    __shared__ float red[256];

    float v[16];
    float lm = -1e30f;
#pragma unroll
    for (int i = 0; i < 16; i++) { v[i] = p[t + 256 * i]; lm = fmaxf(lm, v[i]); }
    red[t] = lm; __syncthreads();
    for (int s = 128; s > 0; s >>= 1) { if (t < s) red[t] = fmaxf(red[t], red[t + s]); __syncthreads(); }
    float M = red[0];
    __syncthreads();
    float ls = 0.f;
#pragma unroll
    for (int i = 0; i < 16; i++) { v[i] = __expf(v[i] - M); ls += v[i]; }
    red[t] = ls; __syncthreads();
    for (int s = 128; s > 0; s >>= 1) { if (t < s) red[t] += red[t + s]; __syncthreads(); }
    float inv = 1.f / red[0];
#pragma unroll
    for (int i = 0; i < 16; i++) p[t + 256 * i] = v[i] * inv;
}

// ---------------------------------------------------------------------------
// Pass 3c: partial sampled over one j-quarter.
// grid (8 ktiles, 4 jq, B), 256 threads. tc4 = t%16 owns 4 c's (float4),
// tk = t/16 owns rows {tk, tk+16}. Inner: 3 LDS : 8 FFMA.
// ---------------------------------------------------------------------------
__global__ void sampled_kernel(const float* __restrict__ L, const float* __restrict__ attn) {
    __shared__ __align__(16) float XT[64 * 68];   // [jj][c], 68-pad (16B rows)
    __shared__ float Pt[32 * 64];                 // [k][jj]
    const int b  = blockIdx.z;
    const int k0 = blockIdx.x * 32;
    const int jbase = blockIdx.y * 1024;
    const int t  = threadIdx.x;
    const int tc4 = t & 15, tk = t >> 4;
    const float* Lb = L + (size_t)b * CC * NN;

    float4 acc0 = make_float4(0.f, 0.f, 0.f, 0.f);
    float4 acc1 = make_float4(0.f, 0.f, 0.f, 0.f);

    for (int jst = 0; jst < 16; jst++) {
        __syncthreads();
        for (int idx = t; idx < 64 * 64; idx += 256) {
            int c = idx >> 6, jj = idx & 63;
            XT[jj * 68 + c] = Lb[(size_t)c * NN + jbase + jst * 64 + jj];
        }
        for (int idx = t; idx < 32 * 64; idx += 256) {
            int kk = idx >> 6, jj = idx & 63;
            Pt[kk * 64 + jj] = attn[((size_t)b * KK + k0 + kk) * NN + jbase + jst * 64 + jj];
        }
        __syncthreads();
#pragma unroll 8
        for (int jj = 0; jj < 64; jj++) {
            float p0 = Pt[tk * 64 + jj];
            float p1 = Pt[(tk + 16) * 64 + jj];
            float4 x = *(const float4*)&XT[jj * 68 + tc4 * 4];
            acc0.x += p0 * x.x; acc0.y += p0 * x.y; acc0.z += p0 * x.z; acc0.w += p0 * x.w;
            acc1.x += p1 * x.x; acc1.y += p1 * x.y; acc1.z += p1 * x.z; acc1.w += p1 * x.w;
        }
    }
    int q = blockIdx.y;
    *(float4*)&g_samp4[q][((size_t)b * KK + k0 + tk) * CC + tc4 * 4] = acc0;
    *(float4*)&g_samp4[q][((size_t)b * KK + k0 + tk + 16) * CC + tc4 * 4] = acc1;
}

// ---------------------------------------------------------------------------
// Pass 4: MLP + L2 normalize, 8 rows per block. 128 blocks x 256 threads.
// ---------------------------------------------------------------------------
__global__ void mlp_kernel(const float* __restrict__ w1, const float* __restrict__ b1,
                           const float* __restrict__ w2, const float* __restrict__ b2,
                           float* __restrict__ emb) {
    __shared__ float s[8 * 64];
    __shared__ float h[8 * 256];
    __shared__ float red[256];
    const int R0 = blockIdx.x * 8;
    const int t = threadIdx.x;

    for (int idx = t; idx < 8 * 64; idx += 256) {
        int r = idx >> 6, c = idx & 63;
        size_t off = (size_t)(R0 + r) * CC + c;
        s[r * 64 + c] = g_samp4[0][off] + g_samp4[1][off] + g_samp4[2][off] + g_samp4[3][off];
    }
    __syncthreads();

    float a1[8];
#pragma unroll
    for (int r = 0; r < 8; r++) a1[r] = b1[t];
#pragma unroll 4
    for (int c = 0; c < CC; c++) {
        float wv = w1[c * PP + t];
#pragma unroll
        for (int r = 0; r < 8; r++) a1[r] += s[r * 64 + c] * wv;
    }
#pragma unroll
    for (int r = 0; r < 8; r++) h[r * 256 + t] = fmaxf(a1[r], 0.f);
    __syncthreads();

    float a2[8];
#pragma unroll
    for (int r = 0; r < 8; r++) a2[r] = b2[t];
#pragma unroll 4
    for (int p2 = 0; p2 < PP; p2++) {
        float wv = w2[p2 * PP + t];
#pragma unroll
        for (int r = 0; r < 8; r++) a2[r] += h[r * 256 + p2] * wv;
    }

    for (int r = 0; r < 8; r++) {
        red[t] = a2[r] * a2[r];
        __syncthreads();
        for (int sd = 128; sd > 0; sd >>= 1) { if (t < sd) red[t] += red[t + sd]; __syncthreads(); }
        float denom = fmaxf(sqrtf(red[0]), 1e-12f);
        __syncthreads();
        emb[(size_t)(R0 + r) * PP + t] = a2[r] / denom;
    }
}

// ---------------------------------------------------------------------------
extern "C" void kernel_launch(void* const* d_in, const int* in_sizes, int n_in,
                              void* d_out, int out_size) {
    const float* L  = (const float*)d_in[0];
    const float* w1 = (const float*)d_in[1];
    const float* b1 = (const float*)d_in[2];
    const float* w2 = (const float*)d_in[3];
    const float* b2 = (const float*)d_in[4];

    float* out  = (float*)d_out;
    float* emb  = out;                                   // [B,K,P]
    float* attn = out + (size_t)BB * KK * PP;            // [B,K,N]
    float* oidx = attn + (size_t)BB * KK * NN;           // [B,K]

    entropy_kernel<<<dim3(32, 2, BB), 256>>>(L);
    sort_kernel<<<BB, 1024>>>(oidx);
    scores_kernel<<<dim3(16, 2, BB), 256>>>(L, attn);
    softmax_kernel<<<BB * KK, 256>>>(attn);
    sampled_kernel<<<dim3(8, 4, BB), 256>>>(L, attn);
    mlp_kernel<<<128, 256>>>(w1, b1, w2, b2, emb);
}

// round 6
// speedup vs baseline: 2.4565x; 1.2353x over previous
#include <cuda_runtime.h>
#include <math.h>
#include <stdint.h>

#define BB 4
#define CC 64
#define NN 4096
#define KK 256
#define PP 256
#define NTILE 32            // 4096 / 128
#define NPAIRS 528          // 32*33/2 upper-triangle tiles

// Scratch (no allocs allowed) ------------------------------------------------
__device__ float g_pm[BB][NTILE][NN];      // partial row max, by opposing slot
__device__ float g_pz[BB][NTILE][NN];      // partial Z
__device__ float g_pt[BB][NTILE][NN];      // partial T = sum s*e^s
__device__ int   g_sel[BB * KK];           // selected row indices (sorted)
__device__ float g_samp4[4][BB * KK * CC]; // j-quarter partials of sampled

// ---------------------------------------------------------------------------
// Pass 1: symmetric-tile entropy stats. One block per (it<=jt) 128x128 tile.
// grid (528, BB), 256 threads, 48 KB static smem.
// Thread (ty,tx) = (t/16, t%16): rows i = it*128 + ty*8 + u (u<8),
// cols j = jt*128 + h*64 + tx*4 + v (v<4), two halves h.
// Row stats -> slot jt; col (transpose) stats -> slot it (skipped on diagonal).
// ---------------------------------------------------------------------------
__global__ void __launch_bounds__(256, 3)
entropy_kernel(const float* __restrict__ L) {
    __shared__ __align__(16) float Xi[64 * 128];  // 32 KB [c][ii]
    __shared__ __align__(16) float Xj[64 * 64];   // 16 KB [c][jj] + col scratch

    // decode upper-triangle pair
    int rem = blockIdx.x, it = 0;
    while (rem >= NTILE - it) { rem -= NTILE - it; it++; }
    const int jt = it + rem;

    const int b = blockIdx.y;
    const int t = threadIdx.x;
    const int tx = t & 15, ty = t >> 4;
    const int i0 = it * 128, j0 = jt * 128;
    const float* Lb = L + (size_t)b * CC * NN;
    const bool offdiag = (it != jt);

    for (int idx = t; idx < 2048; idx += 256) {          // 64*128 floats /4
        int c = idx >> 5, q = idx & 31;
        ((float4*)Xi)[c * 32 + q] = ((const float4*)(Lb + (size_t)c * NN + i0))[q];
    }

    float m[8], z[8], tq[8];
#pragma unroll
    for (int u = 0; u < 8; u++) { m[u] = -1e30f; z[u] = 0.f; tq[u] = 0.f; }

    for (int h = 0; h < 2; h++) {
        __syncthreads();
        for (int idx = t; idx < 1024; idx += 256) {      // 64*64 /4
            int c = idx >> 4, q = idx & 15;
            ((float4*)Xj)[c * 16 + q] =
                ((const float4*)(Lb + (size_t)c * NN + j0 + h * 64))[q];
        }
        __syncthreads();

        float acc[8][4];
#pragma unroll
        for (int u = 0; u < 8; u++)
#pragma unroll
            for (int v = 0; v < 4; v++) acc[u][v] = 0.f;

#pragma unroll 8
        for (int c = 0; c < 64; c++) {
            float4 a0 = *(const float4*)&Xi[c * 128 + ty * 8];
            float4 a1 = *(const float4*)&Xi[c * 128 + ty * 8 + 4];
            float4 bv = *(const float4*)&Xj[c * 64 + tx * 4];
            float a[8] = {a0.x, a0.y, a0.z, a0.w, a1.x, a1.y, a1.z, a1.w};
            float bb[4] = {bv.x, bv.y, bv.z, bv.w};
#pragma unroll
            for (int u = 0; u < 8; u++)
#pragma unroll
                for (int v = 0; v < 4; v++) acc[u][v] += a[u] * bb[v];
        }

        // row-stat online update
#pragma unroll
        for (int u = 0; u < 8; u++) {
            float lm = fmaxf(fmaxf(acc[u][0], acc[u][1]), fmaxf(acc[u][2], acc[u][3]));
            float nm = fmaxf(m[u], lm);
            float sc = __expf(m[u] - nm);
            float zn = z[u] * sc;
            float tn = (tq[u] + z[u] * (m[u] - nm)) * sc;
#pragma unroll
            for (int v = 0; v < 4; v++) {
                float s = acc[u][v] - nm;
                float e = __expf(s);
                zn += e; tn += s * e;
            }
            m[u] = nm; z[u] = zn; tq[u] = tn;
        }

        // col (transpose) stats: reduce over this thread's 8 rows, merge over ty
        if (offdiag) {
            __syncthreads();                 // done reading Xj; reuse as scratch
            float* scm = Xj;                 // [16][64]
            float* scz = Xj + 1024;
            float* sct = Xj + 2048;
#pragma unroll
            for (int v = 0; v < 4; v++) {
                float mc = acc[0][v];
#pragma unroll
                for (int u = 1; u < 8; u++) mc = fmaxf(mc, acc[u][v]);
                float zc = 0.f, tc = 0.f;
#pragma unroll
                for (int u = 0; u < 8; u++) {
                    float s = acc[u][v] - mc;
                    float e = __expf(s);
                    zc += e; tc += s * e;
                }
                int cl = tx * 4 + v;
                scm[ty * 64 + cl] = mc; scz[ty * 64 + cl] = zc; sct[ty * 64 + cl] = tc;
            }
            __syncthreads();
            if (t < 64) {
                float M = scm[t], Z = scz[t], T = sct[t];
                for (int g = 1; g < 16; g++) {
                    float mi = scm[g * 64 + t], zi = scz[g * 64 + t], ti = sct[g * 64 + t];
                    float nm = fmaxf(M, mi);
                    float e1 = __expf(M - nm), e2 = __expf(mi - nm);
                    T = (T + Z * (M - nm)) * e1 + (ti + zi * (mi - nm)) * e2;
                    Z = Z * e1 + zi * e2;
                    M = nm;
                }
                int row = j0 + h * 64 + t;
                g_pm[b][it][row] = M; g_pz[b][it][row] = Z; g_pt[b][it][row] = T;
            }
        }
    }

    // row merge across tx (warp-shuffle butterfly over 16 lanes), write slot jt
#pragma unroll
    for (int u = 0; u < 8; u++) {
        float M = m[u], Z = z[u], T = tq[u];
#pragma unroll
        for (int d = 8; d >= 1; d >>= 1) {
            float Mo = __shfl_xor_sync(0xffffffff, M, d);
            float Zo = __shfl_xor_sync(0xffffffff, Z, d);
            float To = __shfl_xor_sync(0xffffffff, T, d);
            float nm = fmaxf(M, Mo);
            float e1 = __expf(M - nm), e2 = __expf(Mo - nm);
            T = (T + Z * (M - nm)) * e1 + (To + Zo * (Mo - nm)) * e2;
            Z = Z * e1 + Zo * e2;
            M = nm;
        }
        if (tx == 0) {
            int row = i0 + ty * 8 + u;
            g_pm[b][jt][row] = M; g_pz[b][jt][row] = Z; g_pt[b][jt][row] = T;
        }
    }
}

// ---------------------------------------------------------------------------
// Pass 2: merge 32 slot-partials -> entropy, then per-batch bitonic argsort
// (stable via (key, index) lexicographic compare). 4 blocks x 1024 threads.
// ---------------------------------------------------------------------------
__global__ void sort_kernel(float* __restrict__ out_idx) {
    __shared__ float key[NN];
    __shared__ int   val[NN];
    const int b = blockIdx.x, t = threadIdx.x;
    for (int i = t; i < NN; i += 1024) {
        float M = g_pm[b][0][i], Z = g_pz[b][0][i], T = g_pt[b][0][i];
        for (int s = 1; s < NTILE; s++) {
            float mi = g_pm[b][s][i], zi = g_pz[b][s][i], ti = g_pt[b][s][i];
            float nm = fmaxf(M, mi);
            float e1 = __expf(M - nm), e2 = __expf(mi - nm);
            T = (T + Z * (M - nm)) * e1 + (ti + zi * (mi - nm)) * e2;
            Z = Z * e1 + zi * e2;
            M = nm;
        }
        key[i] = logf(Z) - T / Z;
        val[i] = i;
    }
    __syncthreads();
    for (int k = 2; k <= NN; k <<= 1) {
        for (int j = k >> 1; j > 0; j >>= 1) {
            for (int i = t; i < NN; i += 1024) {
                int ixj = i ^ j;
                if (ixj > i) {
                    bool up = ((i & k) == 0);
                    float ka = key[i], kb = key[ixj];
                    int va = val[i], vb = val[ixj];
                    bool agtb = (ka > kb) || (ka == kb && va > vb);
                    if (agtb == up) {
                        key[i] = kb; key[ixj] = ka;
                        val[i] = vb; val[ixj] = va;
                    }
                }
            }
            __syncthreads();
        }
    }
    if (t < KK) {
        int v = val[t];
        g_sel[b * KK + t] = v;
        out_idx[b * KK + t] = (float)v;
    }
}

// ---------------------------------------------------------------------------
// Pass 3a: raw scores for selected rows (exact fp32) -> attn region.
// grid (16 ktiles, 2 jhalves, B), 256 threads.
// ---------------------------------------------------------------------------
__global__ void scores_kernel(const float* __restrict__ L, float* __restrict__ attn) {
    __shared__ float Xi[64 * 16];
    __shared__ __align__(16) float Xj[64 * 128];
    const int b  = blockIdx.z;
    const int k0 = blockIdx.x * 16;
    const int jbase = blockIdx.y * 2048;
    const int t  = threadIdx.x;
    const int r = t & 15, cg = t >> 4;
    const float* Lb = L + (size_t)b * CC * NN;

    for (int idx = t; idx < 64 * 16; idx += 256) {
        int c = idx >> 4, rr = idx & 15;
        int col = g_sel[b * KK + k0 + rr];
        Xi[c * 16 + rr] = Lb[(size_t)c * NN + col];
    }

    for (int jt = 0; jt < 16; jt++) {
        __syncthreads();
        for (int idx = t; idx < 2048; idx += 256) {
            int c = idx >> 5, q = idx & 31;
            ((float4*)Xj)[c * 32 + q] =
                ((const float4*)(Lb + (size_t)c * NN + jbase + jt * 128))[q];
        }
        __syncthreads();
        float acc[8];
#pragma unroll
        for (int v = 0; v < 8; v++) acc[v] = 0.f;
#pragma unroll 8
        for (int c = 0; c < 64; c++) {
            float a = Xi[c * 16 + r];
            float4 b0 = *(const float4*)&Xj[c * 128 + cg * 8];
            float4 b1 = *(const float4*)&Xj[c * 128 + cg * 8 + 4];
            acc[0] += a * b0.x; acc[1] += a * b0.y; acc[2] += a * b0.z; acc[3] += a * b0.w;
            acc[4] += a * b1.x; acc[5] += a * b1.y; acc[6] += a * b1.z; acc[7] += a * b1.w;
        }
        float* dst = attn + ((size_t)b * KK + k0 + r) * NN + jbase + jt * 128 + cg * 8;
        *(float4*)dst       = make_float4(acc[0], acc[1], acc[2], acc[3]);
        *(float4*)(dst + 4) = make_float4(acc[4], acc[5], acc[6], acc[7]);
    }
}

// ---------------------------------------------------------------------------
// Pass 3b: softmax each selected row in place. 1024 blocks x 256 threads.
// ---------------------------------------------------------------------------
__global__ void softmax_kernel(float* __restrict__ attn) {
    const int row = blockIdx.x;
    float* p = attn + (size_t)row * NN;
    const int t = threadIdx.x;
    __shared__ float red[256];

    float v[16];
    float lm = -1e30f;
#pragma unroll
    for (int i = 0; i < 16; i++) { v[i] = p[t + 256 * i]; lm = fmaxf(lm, v[i]); }
    red[t] = lm; __syncthreads();
    for (int s = 128; s > 0; s >>= 1) { if (t < s) red[t] = fmaxf(red[t], red[t + s]); __syncthreads(); }
    float M = red[0];
    __syncthreads();
    float ls = 0.f;
#pragma unroll
    for (int i = 0; i < 16; i++) { v[i] = __expf(v[i] - M); ls += v[i]; }
    red[t] = ls; __syncthreads();
    for (int s = 128; s > 0; s >>= 1) { if (t < s) red[t] += red[t + s]; __syncthreads(); }
    float inv = 1.f / red[0];
#pragma unroll
    for (int i = 0; i < 16; i++) p[t + 256 * i] = v[i] * inv;
}

// ---------------------------------------------------------------------------
// Pass 3c: partial sampled over one j-quarter. grid (8, 4, B), 256 threads.
// ---------------------------------------------------------------------------
__global__ void sampled_kernel(const float* __restrict__ L, const float* __restrict__ attn) {
    __shared__ __align__(16) float XT[64 * 68];
    __shared__ float Pt[32 * 64];
    const int b  = blockIdx.z;
    const int k0 = blockIdx.x * 32;
    const int jbase = blockIdx.y * 1024;
    const int t  = threadIdx.x;
    const int tc4 = t & 15, tk = t >> 4;
    const float* Lb = L + (size_t)b * CC * NN;

    float4 acc0 = make_float4(0.f, 0.f, 0.f, 0.f);
    float4 acc1 = make_float4(0.f, 0.f, 0.f, 0.f);

    for (int jst = 0; jst < 16; jst++) {
        __syncthreads();
        for (int idx = t; idx < 64 * 64; idx += 256) {
            int c = idx >> 6, jj = idx & 63;
            XT[jj * 68 + c] = Lb[(size_t)c * NN + jbase + jst * 64 + jj];
        }
        for (int idx = t; idx < 32 * 64; idx += 256) {
            int kk = idx >> 6, jj = idx & 63;
            Pt[kk * 64 + jj] = attn[((size_t)b * KK + k0 + kk) * NN + jbase + jst * 64 + jj];
        }
        __syncthreads();
#pragma unroll 8
        for (int jj = 0; jj < 64; jj++) {
            float p0 = Pt[tk * 64 + jj];
            float p1 = Pt[(tk + 16) * 64 + jj];
            float4 x = *(const float4*)&XT[jj * 68 + tc4 * 4];
            acc0.x += p0 * x.x; acc0.y += p0 * x.y; acc0.z += p0 * x.z; acc0.w += p0 * x.w;
            acc1.x += p1 * x.x; acc1.y += p1 * x.y; acc1.z += p1 * x.z; acc1.w += p1 * x.w;
        }
    }
    int q = blockIdx.y;
    *(float4*)&g_samp4[q][((size_t)b * KK + k0 + tk) * CC + tc4 * 4] = acc0;
    *(float4*)&g_samp4[q][((size_t)b * KK + k0 + tk + 16) * CC + tc4 * 4] = acc1;
}

// ---------------------------------------------------------------------------
// Pass 4: MLP + L2 normalize, 8 rows per block. 128 blocks x 256 threads.
// ---------------------------------------------------------------------------
__global__ void mlp_kernel(const float* __restrict__ w1, const float* __restrict__ b1,
                           const float* __restrict__ w2, const float* __restrict__ b2,
                           float* __restrict__ emb) {
    __shared__ float s[8 * 64];
    __shared__ float h[8 * 256];
    __shared__ float red[256];
    const int R0 = blockIdx.x * 8;
    const int t = threadIdx.x;

    for (int idx = t; idx < 8 * 64; idx += 256) {
        int r = idx >> 6, c = idx & 63;
        size_t off = (size_t)(R0 + r) * CC + c;
        s[r * 64 + c] = g_samp4[0][off] + g_samp4[1][off] + g_samp4[2][off] + g_samp4[3][off];
    }
    __syncthreads();

    float a1[8];
#pragma unroll
    for (int r = 0; r < 8; r++) a1[r] = b1[t];
#pragma unroll 4
    for (int c = 0; c < CC; c++) {
        float wv = w1[c * PP + t];
#pragma unroll
        for (int r = 0; r < 8; r++) a1[r] += s[r * 64 + c] * wv;
    }
#pragma unroll
    for (int r = 0; r < 8; r++) h[r * 256 + t] = fmaxf(a1[r], 0.f);
    __syncthreads();

    float a2[8];
#pragma unroll
    for (int r = 0; r < 8; r++) a2[r] = b2[t];
#pragma unroll 4
    for (int p2 = 0; p2 < PP; p2++) {
        float wv = w2[p2 * PP + t];
#pragma unroll
        for (int r = 0; r < 8; r++) a2[r] += h[r * 256 + p2] * wv;
    }

    for (int r = 0; r < 8; r++) {
        red[t] = a2[r] * a2[r];
        __syncthreads();
        for (int sd = 128; sd > 0; sd >>= 1) { if (t < sd) red[t] += red[t + sd]; __syncthreads(); }
        float denom = fmaxf(sqrtf(red[0]), 1e-12f);
        __syncthreads();
        emb[(size_t)(R0 + r) * PP + t] = a2[r] / denom;
    }
}

// ---------------------------------------------------------------------------
extern "C" void kernel_launch(void* const* d_in, const int* in_sizes, int n_in,
                              void* d_out, int out_size) {
    const float* L  = (const float*)d_in[0];
    const float* w1 = (const float*)d_in[1];
    const float* b1 = (const float*)d_in[2];
    const float* w2 = (const float*)d_in[3];
    const float* b2 = (const float*)d_in[4];

    float* out  = (float*)d_out;
    float* emb  = out;                                   // [B,K,P]
    float* attn = out + (size_t)BB * KK * PP;            // [B,K,N]
    float* oidx = attn + (size_t)BB * KK * NN;           // [B,K]

    entropy_kernel<<<dim3(NPAIRS, BB), 256>>>(L);
    sort_kernel<<<BB, 1024>>>(oidx);
    scores_kernel<<<dim3(16, 2, BB), 256>>>(L, attn);
    softmax_kernel<<<BB * KK, 256>>>(attn);
    sampled_kernel<<<dim3(8, 4, BB), 256>>>(L, attn);
    mlp_kernel<<<128, 256>>>(w1, b1, w2, b2, emb);
}

// round 7
// speedup vs baseline: 2.7231x; 1.1085x over previous
#include <cuda_runtime.h>
#include <math.h>
#include <stdint.h>

#define BB 4
#define CC 64
#define NN 4096
#define KK 256
#define PP 256
#define NTILE 32            // 4096 / 128
#define NPAIRS 528          // 32*33/2 upper-triangle tiles

// Scratch (no allocs allowed) ------------------------------------------------
__device__ float g_diag[BB][NN];           // o_i = ||x_i||^2
__device__ float g_pz[BB][NTILE][NN];      // partial Z (additive, by slot)
__device__ float g_pt[BB][NTILE][NN];      // partial T = sum (s-o)e^(s-o)
__device__ int   g_sel[BB * KK];           // selected row indices (sorted)
__device__ float g_Zp[2][BB * KK];         // per-jhalf partial Z of selected rows
__device__ float g_samp4[4][BB * KK * CC]; // j-quarter partials of sampled

// ---------------------------------------------------------------------------
// Pass 0: diagonal o_i = sum_c x^2. grid (4, BB), 1024 threads.
// ---------------------------------------------------------------------------
__global__ void diag_kernel(const float* __restrict__ L) {
    const int b = blockIdx.y;
    const int i = blockIdx.x * 1024 + threadIdx.x;
    const float* Lb = L + (size_t)b * CC * NN;
    float acc = 0.f;
#pragma unroll 8
    for (int c = 0; c < CC; c++) {
        float v = Lb[(size_t)c * NN + i];
        acc += v * v;
    }
    g_diag[b][i] = acc;
}

// ---------------------------------------------------------------------------
// Pass 1: symmetric-tile softmax stats with fixed diag offsets (additive).
// One block per (it<=jt) 128x128 tile. grid (528, BB), 256 threads.
// Thread (ty,tx): rows i = it*128 + ty*8 + u (u<8),
// cols j = jt*128 + h*64 + tx*4 + v (v<4), two halves h.
// Row (Z,T) -> slot jt; col (transpose) (Z,T) -> slot it (skipped on diagonal).
// ---------------------------------------------------------------------------
__global__ void __launch_bounds__(256, 3)
entropy_kernel(const float* __restrict__ L) {
    __shared__ __align__(16) float Xi[64 * 128];  // 32 KB [c][ii]
    __shared__ __align__(16) float Xj[64 * 64];   // 16 KB [c][jj] + scratch

    // decode upper-triangle pair
    int rem = blockIdx.x, it = 0;
    while (rem >= NTILE - it) { rem -= NTILE - it; it++; }
    const int jt = it + rem;

    const int b = blockIdx.y;
    const int t = threadIdx.x;
    const int tx = t & 15, ty = t >> 4;
    const int i0 = it * 128, j0 = jt * 128;
    const float* Lb = L + (size_t)b * CC * NN;
    const bool offdiag = (it != jt);

    for (int idx = t; idx < 2048; idx += 256) {          // 64*128 floats /4
        int c = idx >> 5, q = idx & 31;
        ((float4*)Xi)[c * 32 + q] = ((const float4*)(Lb + (size_t)c * NN + i0))[q];
    }

    float oi[8];
    {
        float4 o0 = *(const float4*)&g_diag[b][i0 + ty * 8];
        float4 o1 = *(const float4*)&g_diag[b][i0 + ty * 8 + 4];
        oi[0] = o0.x; oi[1] = o0.y; oi[2] = o0.z; oi[3] = o0.w;
        oi[4] = o1.x; oi[5] = o1.y; oi[6] = o1.z; oi[7] = o1.w;
    }

    float z[8], tq[8];
#pragma unroll
    for (int u = 0; u < 8; u++) { z[u] = 0.f; tq[u] = 0.f; }

    for (int h = 0; h < 2; h++) {
        __syncthreads();
        for (int idx = t; idx < 1024; idx += 256) {      // 64*64 /4
            int c = idx >> 4, q = idx & 15;
            ((float4*)Xj)[c * 16 + q] =
                ((const float4*)(Lb + (size_t)c * NN + j0 + h * 64))[q];
        }
        __syncthreads();

        float acc[8][4];
#pragma unroll
        for (int u = 0; u < 8; u++)
#pragma unroll
            for (int v = 0; v < 4; v++) acc[u][v] = 0.f;

#pragma unroll 8
        for (int c = 0; c < 64; c++) {
            float4 a0 = *(const float4*)&Xi[c * 128 + ty * 8];
            float4 a1 = *(const float4*)&Xi[c * 128 + ty * 8 + 4];
            float4 bv = *(const float4*)&Xj[c * 64 + tx * 4];
            float a[8] = {a0.x, a0.y, a0.z, a0.w, a1.x, a1.y, a1.z, a1.w};
            float bb[4] = {bv.x, bv.y, bv.z, bv.w};
#pragma unroll
            for (int u = 0; u < 8; u++)
#pragma unroll
                for (int v = 0; v < 4; v++) acc[u][v] += a[u] * bb[v];
        }

        // row side: additive (Z, T) with fixed offset oi[u]
#pragma unroll
        for (int u = 0; u < 8; u++)
#pragma unroll
            for (int v = 0; v < 4; v++) {
                float s = acc[u][v] - oi[u];
                float e = __expf(s);
                z[u] += e; tq[u] += s * e;
            }

        // col (transpose) side: offsets o_j, reduce over u then over ty
        if (offdiag) {
            float4 ojv = *(const float4*)&g_diag[b][j0 + h * 64 + tx * 4];
            float oj[4] = {ojv.x, ojv.y, ojv.z, ojv.w};
            __syncthreads();                 // done reading Xj; reuse as scratch
            float* scz = Xj;                 // [16][64]
            float* sct = Xj + 1024;
#pragma unroll
            for (int v = 0; v < 4; v++) {
                float zc = 0.f, tc = 0.f;
#pragma unroll
                for (int u = 0; u < 8; u++) {
                    float s = acc[u][v] - oj[v];
                    float e = __expf(s);
                    zc += e; tc += s * e;
                }
                int cl = tx * 4 + v;
                scz[ty * 64 + cl] = zc; sct[ty * 64 + cl] = tc;
            }
            __syncthreads();
            if (t < 64) {
                float Z = 0.f, T = 0.f;
#pragma unroll 4
                for (int g = 0; g < 16; g++) {
                    Z += scz[g * 64 + t];
                    T += sct[g * 64 + t];
                }
                int row = j0 + h * 64 + t;
                g_pz[b][it][row] = Z; g_pt[b][it][row] = T;
            }
        }
    }

    // row merge across tx: plain shuffle adds over 16 lanes, write slot jt
#pragma unroll
    for (int u = 0; u < 8; u++) {
        float Z = z[u], T = tq[u];
#pragma unroll
        for (int d = 8; d >= 1; d >>= 1) {
            Z += __shfl_xor_sync(0xffffffff, Z, d);
            T += __shfl_xor_sync(0xffffffff, T, d);
        }
        if (tx == 0) {
            int row = i0 + ty * 8 + u;
            g_pz[b][jt][row] = Z; g_pt[b][jt][row] = T;
        }
    }
}

// ---------------------------------------------------------------------------
// Pass 2: sum 32 slot-partials -> entropy, then per-batch bitonic argsort
// (stable via (key, index) lexicographic compare). 4 blocks x 1024 threads.
// ---------------------------------------------------------------------------
__global__ void sort_kernel(float* __restrict__ out_idx) {
    __shared__ float key[NN];
    __shared__ int   val[NN];
    const int b = blockIdx.x, t = threadIdx.x;
    for (int i = t; i < NN; i += 1024) {
        float Z = 0.f, T = 0.f;
#pragma unroll 8
        for (int s = 0; s < NTILE; s++) {
            Z += g_pz[b][s][i];
            T += g_pt[b][s][i];
        }
        key[i] = logf(Z) - T / Z;
        val[i] = i;
    }
    __syncthreads();
    for (int k = 2; k <= NN; k <<= 1) {
        for (int j = k >> 1; j > 0; j >>= 1) {
            for (int i = t; i < NN; i += 1024) {
                int ixj = i ^ j;
                if (ixj > i) {
                    bool up = ((i & k) == 0);
                    float ka = key[i], kb = key[ixj];
                    int va = val[i], vb = val[ixj];
                    bool agtb = (ka > kb) || (ka == kb && va > vb);
                    if (agtb == up) {
                        key[i] = kb; key[ixj] = ka;
                        val[i] = vb; val[ixj] = va;
                    }
                }
            }
            __syncthreads();
        }
    }
    if (t < KK) {
        int v = val[t];
        g_sel[b * KK + t] = v;
        out_idx[b * KK + t] = (float)v;
    }
}

// ---------------------------------------------------------------------------
// Pass 3a: u = exp(s - o_k) for selected rows -> attn region, + partial Z.
// grid (16 ktiles, 2 jhalves, B), 256 threads.
// ---------------------------------------------------------------------------
__global__ void scores_kernel(const float* __restrict__ L, float* __restrict__ attn) {
    __shared__ float Xi[64 * 16];
    __shared__ float Ob[16];
    __shared__ __align__(16) float Xj[64 * 128];
    __shared__ float zred[16][17];
    const int b  = blockIdx.z;
    const int k0 = blockIdx.x * 16;
    const int jh = blockIdx.y;
    const int jbase = jh * 2048;
    const int t  = threadIdx.x;
    const int r = t & 15, cg = t >> 4;
    const float* Lb = L + (size_t)b * CC * NN;

    for (int idx = t; idx < 64 * 16; idx += 256) {
        int c = idx >> 4, rr = idx & 15;
        int col = g_sel[b * KK + k0 + rr];
        Xi[c * 16 + rr] = Lb[(size_t)c * NN + col];
    }
    if (t < 16) Ob[t] = g_diag[b][g_sel[b * KK + k0 + t]];

    float zacc = 0.f;
    for (int jt = 0; jt < 16; jt++) {
        __syncthreads();
        for (int idx = t; idx < 2048; idx += 256) {
            int c = idx >> 5, q = idx & 31;
            ((float4*)Xj)[c * 32 + q] =
                ((const float4*)(Lb + (size_t)c * NN + jbase + jt * 128))[q];
        }
        __syncthreads();
        float acc[8];
#pragma unroll
        for (int v = 0; v < 8; v++) acc[v] = 0.f;
#pragma unroll 8
        for (int c = 0; c < 64; c++) {
            float a = Xi[c * 16 + r];
            float4 b0 = *(const float4*)&Xj[c * 128 + cg * 8];
            float4 b1 = *(const float4*)&Xj[c * 128 + cg * 8 + 4];
            acc[0] += a * b0.x; acc[1] += a * b0.y; acc[2] += a * b0.z; acc[3] += a * b0.w;
            acc[4] += a * b1.x; acc[5] += a * b1.y; acc[6] += a * b1.z; acc[7] += a * b1.w;
        }
        float o = Ob[r];
#pragma unroll
        for (int v = 0; v < 8; v++) {
            acc[v] = __expf(acc[v] - o);
            zacc += acc[v];
        }
        float* dst = attn + ((size_t)b * KK + k0 + r) * NN + jbase + jt * 128 + cg * 8;
        *(float4*)dst       = make_float4(acc[0], acc[1], acc[2], acc[3]);
        *(float4*)(dst + 4) = make_float4(acc[4], acc[5], acc[6], acc[7]);
    }
    zred[cg][r] = zacc;
    __syncthreads();
    if (t < 16) {
        float Z = 0.f;
#pragma unroll
        for (int g = 0; g < 16; g++) Z += zred[g][t];
        g_Zp[jh][b * KK + k0 + t] = Z;
    }
}

// ---------------------------------------------------------------------------
// Pass 3b: normalize attn (u -> u/Z) + partial sampled over one j-quarter.
// grid (8 ktiles, 4 jq, B), 256 threads.
// ---------------------------------------------------------------------------
__global__ void norm_sampled_kernel(const float* __restrict__ L, float* __restrict__ attn) {
    __shared__ __align__(16) float XT[64 * 68];
    __shared__ float Pt[32 * 64];
    __shared__ float iZ[32];
    const int b  = blockIdx.z;
    const int k0 = blockIdx.x * 32;
    const int jbase = blockIdx.y * 1024;
    const int t  = threadIdx.x;
    const int tc4 = t & 15, tk = t >> 4;
    const float* Lb = L + (size_t)b * CC * NN;

    if (t < 32)
        iZ[t] = 1.f / (g_Zp[0][b * KK + k0 + t] + g_Zp[1][b * KK + k0 + t]);

    float4 acc0 = make_float4(0.f, 0.f, 0.f, 0.f);
    float4 acc1 = make_float4(0.f, 0.f, 0.f, 0.f);

    for (int jst = 0; jst < 16; jst++) {
        __syncthreads();
        for (int idx = t; idx < 64 * 64; idx += 256) {
            int c = idx >> 6, jj = idx & 63;
            XT[jj * 68 + c] = Lb[(size_t)c * NN + jbase + jst * 64 + jj];
        }
        for (int idx = t; idx < 32 * 64; idx += 256) {
            int kk = idx >> 6, jj = idx & 63;
            Pt[kk * 64 + jj] = attn[((size_t)b * KK + k0 + kk) * NN + jbase + jst * 64 + jj];
        }
        __syncthreads();
        // write back normalized attn (same addresses, from the smem copy)
        for (int idx = t; idx < 32 * 64; idx += 256) {
            int kk = idx >> 6, jj = idx & 63;
            attn[((size_t)b * KK + k0 + kk) * NN + jbase + jst * 64 + jj] =
                Pt[kk * 64 + jj] * iZ[kk];
        }
#pragma unroll 8
        for (int jj = 0; jj < 64; jj++) {
            float p0 = Pt[tk * 64 + jj];
            float p1 = Pt[(tk + 16) * 64 + jj];
            float4 x = *(const float4*)&XT[jj * 68 + tc4 * 4];
            acc0.x += p0 * x.x; acc0.y += p0 * x.y; acc0.z += p0 * x.z; acc0.w += p0 * x.w;
            acc1.x += p1 * x.x; acc1.y += p1 * x.y; acc1.z += p1 * x.z; acc1.w += p1 * x.w;
        }
    }
    float s0 = iZ[tk], s1 = iZ[tk + 16];
    acc0.x *= s0; acc0.y *= s0; acc0.z *= s0; acc0.w *= s0;
    acc1.x *= s1; acc1.y *= s1; acc1.z *= s1; acc1.w *= s1;
    int q = blockIdx.y;
    *(float4*)&g_samp4[q][((size_t)b * KK + k0 + tk) * CC + tc4 * 4] = acc0;
    *(float4*)&g_samp4[q][((size_t)b * KK + k0 + tk + 16) * CC + tc4 * 4] = acc1;
}

// ---------------------------------------------------------------------------
// Pass 4: MLP + L2 normalize, 8 rows per block. 128 blocks x 256 threads.
// ---------------------------------------------------------------------------
__global__ void mlp_kernel(const float* __restrict__ w1, const float* __restrict__ b1,
                           const float* __restrict__ w2, const float* __restrict__ b2,
                           float* __restrict__ emb) {
    __shared__ float s[8 * 64];
    __shared__ float h[8 * 256];
    __shared__ float red[256];
    const int R0 = blockIdx.x * 8;
    const int t = threadIdx.x;

    for (int idx = t; idx < 8 * 64; idx += 256) {
        int r = idx >> 6, c = idx & 63;
        size_t off = (size_t)(R0 + r) * CC + c;
        s[r * 64 + c] = g_samp4[0][off] + g_samp4[1][off] + g_samp4[2][off] + g_samp4[3][off];
    }
    __syncthreads();

    float a1[8];
#pragma unroll
    for (int r = 0; r < 8; r++) a1[r] = b1[t];
#pragma unroll 4
    for (int c = 0; c < CC; c++) {
        float wv = w1[c * PP + t];
#pragma unroll
        for (int r = 0; r < 8; r++) a1[r] += s[r * 64 + c] * wv;
    }
#pragma unroll
    for (int r = 0; r < 8; r++) h[r * 256 + t] = fmaxf(a1[r], 0.f);
    __syncthreads();

    float a2[8];
#pragma unroll
    for (int r = 0; r < 8; r++) a2[r] = b2[t];
#pragma unroll 4
    for (int p2 = 0; p2 < PP; p2++) {
        float wv = w2[p2 * PP + t];
#pragma unroll
        for (int r = 0; r < 8; r++) a2[r] += h[r * 256 + p2] * wv;
    }

    for (int r = 0; r < 8; r++) {
        red[t] = a2[r] * a2[r];
        __syncthreads();
        for (int sd = 128; sd > 0; sd >>= 1) { if (t < sd) red[t] += red[t + sd]; __syncthreads(); }
        float denom = fmaxf(sqrtf(red[0]), 1e-12f);
        __syncthreads();
        emb[(size_t)(R0 + r) * PP + t] = a2[r] / denom;
    }
}

// ---------------------------------------------------------------------------
extern "C" void kernel_launch(void* const* d_in, const int* in_sizes, int n_in,
                              void* d_out, int out_size) {
    const float* L  = (const float*)d_in[0];
    const float* w1 = (const float*)d_in[1];
    const float* b1 = (const float*)d_in[2];
    const float* w2 = (const float*)d_in[3];
    const float* b2 = (const float*)d_in[4];

    float* out  = (float*)d_out;
    float* emb  = out;                                   // [B,K,P]
    float* attn = out + (size_t)BB * KK * PP;            // [B,K,N]
    float* oidx = attn + (size_t)BB * KK * NN;           // [B,K]

    diag_kernel<<<dim3(4, BB), 1024>>>(L);
    entropy_kernel<<<dim3(NPAIRS, BB), 256>>>(L);
    sort_kernel<<<BB, 1024>>>(oidx);
    scores_kernel<<<dim3(16, 2, BB), 256>>>(L, attn);
    norm_sampled_kernel<<<dim3(8, 4, BB), 256>>>(L, attn);
    mlp_kernel<<<128, 256>>>(w1, b1, w2, b2, emb);
}

// round 8
// speedup vs baseline: 2.9111x; 1.0690x over previous
#include <cuda_runtime.h>
#include <math.h>
#include <stdint.h>

#define BB 4
#define CC 64
#define NN 4096
#define KK 256
#define PP 256
#define NTILE 32            // 4096 / 128
#define NPAIRS 528          // 32*33/2 upper-triangle tiles

// Scratch (no allocs allowed) ------------------------------------------------
__device__ float g_diag[BB][NN];           // o_i = ||x_i||^2
__device__ float g_pz[BB][NTILE][NN];      // partial Z (additive, by slot)
__device__ float g_pt[BB][NTILE][NN];      // partial T = sum (s-o)e^(s-o)
__device__ float g_iZ[BB][NN];             // 1/Z per row (from sort pass)
__device__ int   g_sel[BB * KK];           // selected row indices (sorted)
__device__ float g_samp8[8][BB * KK * CC]; // j-eighth partials of sampled

// ---------------------------------------------------------------------------
// Pass 0: diagonal o_i = sum_c x^2. grid (4, BB), 1024 threads.
// ---------------------------------------------------------------------------
__global__ void diag_kernel(const float* __restrict__ L) {
    const int b = blockIdx.y;
    const int i = blockIdx.x * 1024 + threadIdx.x;
    const float* Lb = L + (size_t)b * CC * NN;
    float acc = 0.f;
#pragma unroll 8
    for (int c = 0; c < CC; c++) {
        float v = Lb[(size_t)c * NN + i];
        acc += v * v;
    }
    g_diag[b][i] = acc;
}

// ---------------------------------------------------------------------------
// Pass 1: symmetric-tile softmax stats with fixed diag offsets (additive).
// One block per (it<=jt) 128x128 tile. grid (528, BB), 256 threads.
// Row (Z,T) -> slot jt; col (transpose) (Z,T) -> slot it (skipped on diagonal).
// ---------------------------------------------------------------------------
__global__ void __launch_bounds__(256, 3)
entropy_kernel(const float* __restrict__ L) {
    __shared__ __align__(16) float Xi[64 * 128];  // 32 KB [c][ii]
    __shared__ __align__(16) float Xj[64 * 64];   // 16 KB [c][jj] + scratch

    // decode upper-triangle pair
    int rem = blockIdx.x, it = 0;
    while (rem >= NTILE - it) { rem -= NTILE - it; it++; }
    const int jt = it + rem;

    const int b = blockIdx.y;
    const int t = threadIdx.x;
    const int tx = t & 15, ty = t >> 4;
    const int i0 = it * 128, j0 = jt * 128;
    const float* Lb = L + (size_t)b * CC * NN;
    const bool offdiag = (it != jt);

    for (int idx = t; idx < 2048; idx += 256) {          // 64*128 floats /4
        int c = idx >> 5, q = idx & 31;
        ((float4*)Xi)[c * 32 + q] = ((const float4*)(Lb + (size_t)c * NN + i0))[q];
    }

    float oi[8];
    {
        float4 o0 = *(const float4*)&g_diag[b][i0 + ty * 8];
        float4 o1 = *(const float4*)&g_diag[b][i0 + ty * 8 + 4];
        oi[0] = o0.x; oi[1] = o0.y; oi[2] = o0.z; oi[3] = o0.w;
        oi[4] = o1.x; oi[5] = o1.y; oi[6] = o1.z; oi[7] = o1.w;
    }

    float z[8], tq[8];
#pragma unroll
    for (int u = 0; u < 8; u++) { z[u] = 0.f; tq[u] = 0.f; }

    for (int h = 0; h < 2; h++) {
        __syncthreads();
        for (int idx = t; idx < 1024; idx += 256) {      // 64*64 /4
            int c = idx >> 4, q = idx & 15;
            ((float4*)Xj)[c * 16 + q] =
                ((const float4*)(Lb + (size_t)c * NN + j0 + h * 64))[q];
        }
        __syncthreads();

        float acc[8][4];
#pragma unroll
        for (int u = 0; u < 8; u++)
#pragma unroll
            for (int v = 0; v < 4; v++) acc[u][v] = 0.f;

#pragma unroll 8
        for (int c = 0; c < 64; c++) {
            float4 a0 = *(const float4*)&Xi[c * 128 + ty * 8];
            float4 a1 = *(const float4*)&Xi[c * 128 + ty * 8 + 4];
            float4 bv = *(const float4*)&Xj[c * 64 + tx * 4];
            float a[8] = {a0.x, a0.y, a0.z, a0.w, a1.x, a1.y, a1.z, a1.w};
            float bb[4] = {bv.x, bv.y, bv.z, bv.w};
#pragma unroll
            for (int u = 0; u < 8; u++)
#pragma unroll
                for (int v = 0; v < 4; v++) acc[u][v] += a[u] * bb[v];
        }

        // row side: additive (Z, T) with fixed offset oi[u]
#pragma unroll
        for (int u = 0; u < 8; u++)
#pragma unroll
            for (int v = 0; v < 4; v++) {
                float s = acc[u][v] - oi[u];
                float e = __expf(s);
                z[u] += e; tq[u] += s * e;
            }

        // col (transpose) side: offsets o_j, reduce over u then over ty
        if (offdiag) {
            float4 ojv = *(const float4*)&g_diag[b][j0 + h * 64 + tx * 4];
            float oj[4] = {ojv.x, ojv.y, ojv.z, ojv.w};
            __syncthreads();                 // done reading Xj; reuse as scratch
            float* scz = Xj;                 // [16][64]
            float* sct = Xj + 1024;
#pragma unroll
            for (int v = 0; v < 4; v++) {
                float zc = 0.f, tc = 0.f;
#pragma unroll
                for (int u = 0; u < 8; u++) {
                    float s = acc[u][v] - oj[v];
                    float e = __expf(s);
                    zc += e; tc += s * e;
                }
                int cl = tx * 4 + v;
                scz[ty * 64 + cl] = zc; sct[ty * 64 + cl] = tc;
            }
            __syncthreads();
            if (t < 64) {
                float Z = 0.f, T = 0.f;
#pragma unroll 4
                for (int g = 0; g < 16; g++) {
                    Z += scz[g * 64 + t];
                    T += sct[g * 64 + t];
                }
                int row = j0 + h * 64 + t;
                g_pz[b][it][row] = Z; g_pt[b][it][row] = T;
            }
        }
    }

    // row merge across tx: plain shuffle adds over 16 lanes, write slot jt
#pragma unroll
    for (int u = 0; u < 8; u++) {
        float Z = z[u], T = tq[u];
#pragma unroll
        for (int d = 8; d >= 1; d >>= 1) {
            Z += __shfl_xor_sync(0xffffffff, Z, d);
            T += __shfl_xor_sync(0xffffffff, T, d);
        }
        if (tx == 0) {
            int row = i0 + ty * 8 + u;
            g_pz[b][jt][row] = Z; g_pt[b][jt][row] = T;
        }
    }
}

// ---------------------------------------------------------------------------
// Pass 2: sum 32 slot-partials -> entropy + 1/Z, then per-batch bitonic
// argsort (stable via (key, index) lexicographic). 4 blocks x 1024 threads.
// ---------------------------------------------------------------------------
__global__ void sort_kernel(float* __restrict__ out_idx) {
    __shared__ float key[NN];
    __shared__ int   val[NN];
    const int b = blockIdx.x, t = threadIdx.x;
    for (int i = t; i < NN; i += 1024) {
        float Z = 0.f, T = 0.f;
#pragma unroll 8
        for (int s = 0; s < NTILE; s++) {
            Z += g_pz[b][s][i];
            T += g_pt[b][s][i];
        }
        key[i] = logf(Z) - T / Z;
        g_iZ[b][i] = 1.f / Z;
        val[i] = i;
    }
    __syncthreads();
    for (int k = 2; k <= NN; k <<= 1) {
        for (int j = k >> 1; j > 0; j >>= 1) {
            for (int i = t; i < NN; i += 1024) {
                int ixj = i ^ j;
                if (ixj > i) {
                    bool up = ((i & k) == 0);
                    float ka = key[i], kb = key[ixj];
                    int va = val[i], vb = val[ixj];
                    bool agtb = (ka > kb) || (ka == kb && va > vb);
                    if (agtb == up) {
                        key[i] = kb; key[ixj] = ka;
                        val[i] = vb; val[ixj] = va;
                    }
                }
            }
            __syncthreads();
        }
    }
    if (t < KK) {
        int v = val[t];
        g_sel[b * KK + t] = v;
        out_idx[b * KK + t] = (float)v;
    }
}

// ---------------------------------------------------------------------------
// Pass 3a: attn = exp(s - o_k) / Z for selected rows (final, normalized).
// grid (16 ktiles, 4 jquarters, B), 256 threads. r = t%16, cg = t/16.
// ---------------------------------------------------------------------------
__global__ void scores_kernel(const float* __restrict__ L, float* __restrict__ attn) {
    __shared__ float Xi[64 * 16];
    __shared__ float Ob[16];
    __shared__ float Zb[16];
    __shared__ __align__(16) float Xj[64 * 128];
    const int b  = blockIdx.z;
    const int k0 = blockIdx.x * 16;
    const int jbase = blockIdx.y * 1024;
    const int t  = threadIdx.x;
    const int r = t & 15, cg = t >> 4;
    const float* Lb = L + (size_t)b * CC * NN;

    for (int idx = t; idx < 64 * 16; idx += 256) {
        int c = idx >> 4, rr = idx & 15;
        int col = g_sel[b * KK + k0 + rr];
        Xi[c * 16 + rr] = Lb[(size_t)c * NN + col];
    }
    if (t < 16) {
        int col = g_sel[b * KK + k0 + t];
        Ob[t] = g_diag[b][col];
        Zb[t] = g_iZ[b][col];
    }

    for (int jt = 0; jt < 8; jt++) {
        __syncthreads();
        for (int idx = t; idx < 2048; idx += 256) {
            int c = idx >> 5, q = idx & 31;
            ((float4*)Xj)[c * 32 + q] =
                ((const float4*)(Lb + (size_t)c * NN + jbase + jt * 128))[q];
        }
        __syncthreads();
        float acc[8];
#pragma unroll
        for (int v = 0; v < 8; v++) acc[v] = 0.f;
#pragma unroll 8
        for (int c = 0; c < 64; c++) {
            float a = Xi[c * 16 + r];
            float4 b0 = *(const float4*)&Xj[c * 128 + cg * 8];
            float4 b1 = *(const float4*)&Xj[c * 128 + cg * 8 + 4];
            acc[0] += a * b0.x; acc[1] += a * b0.y; acc[2] += a * b0.z; acc[3] += a * b0.w;
            acc[4] += a * b1.x; acc[5] += a * b1.y; acc[6] += a * b1.z; acc[7] += a * b1.w;
        }
        float o = Ob[r], iz = Zb[r];
#pragma unroll
        for (int v = 0; v < 8; v++) acc[v] = __expf(acc[v] - o) * iz;
        float* dst = attn + ((size_t)b * KK + k0 + r) * NN + jbase + jt * 128 + cg * 8;
        *(float4*)dst       = make_float4(acc[0], acc[1], acc[2], acc[3]);
        *(float4*)(dst + 4) = make_float4(acc[4], acc[5], acc[6], acc[7]);
    }
}

// ---------------------------------------------------------------------------
// Pass 3b: partial sampled over one j-eighth (attn already normalized).
// grid (8 ktiles, 8 jo, B), 256 threads. tc4 = t%16 (4 c), tk = t>>4 (2 k).
// ---------------------------------------------------------------------------
__global__ void sampled_kernel(const float* __restrict__ L, const float* __restrict__ attn) {
    __shared__ __align__(16) float XT[64 * 68];   // [jj][c], 68-pad
    __shared__ float Pt[32 * 64];                 // [k][jj]
    const int b  = blockIdx.z;
    const int k0 = blockIdx.x * 32;
    const int jbase = blockIdx.y * 512;
    const int t  = threadIdx.x;
    const int tc4 = t & 15, tk = t >> 4;
    const float* Lb = L + (size_t)b * CC * NN;

    float4 acc0 = make_float4(0.f, 0.f, 0.f, 0.f);
    float4 acc1 = make_float4(0.f, 0.f, 0.f, 0.f);

    for (int jst = 0; jst < 8; jst++) {
        __syncthreads();
        for (int idx = t; idx < 64 * 64; idx += 256) {
            int c = idx >> 6, jj = idx & 63;
            XT[jj * 68 + c] = Lb[(size_t)c * NN + jbase + jst * 64 + jj];
        }
        for (int idx = t; idx < 32 * 64; idx += 256) {
            int kk = idx >> 6, jj = idx & 63;
            Pt[kk * 64 + jj] = attn[((size_t)b * KK + k0 + kk) * NN + jbase + jst * 64 + jj];
        }
        __syncthreads();
#pragma unroll 8
        for (int jj = 0; jj < 64; jj++) {
            float p0 = Pt[tk * 64 + jj];
            float p1 = Pt[(tk + 16) * 64 + jj];
            float4 x = *(const float4*)&XT[jj * 68 + tc4 * 4];
            acc0.x += p0 * x.x; acc0.y += p0 * x.y; acc0.z += p0 * x.z; acc0.w += p0 * x.w;
            acc1.x += p1 * x.x; acc1.y += p1 * x.y; acc1.z += p1 * x.z; acc1.w += p1 * x.w;
        }
    }
    int q = blockIdx.y;
    *(float4*)&g_samp8[q][((size_t)b * KK + k0 + tk) * CC + tc4 * 4] = acc0;
    *(float4*)&g_samp8[q][((size_t)b * KK + k0 + tk + 16) * CC + tc4 * 4] = acc1;
}

// ---------------------------------------------------------------------------
// Pass 4: MLP + L2 normalize, 8 rows per block. 128 blocks x 256 threads.
// ---------------------------------------------------------------------------
__global__ void mlp_kernel(const float* __restrict__ w1, const float* __restrict__ b1,
                           const float* __restrict__ w2, const float* __restrict__ b2,
                           float* __restrict__ emb) {
    __shared__ float s[8 * 64];
    __shared__ float h[8 * 256];
    __shared__ float red[256];
    const int R0 = blockIdx.x * 8;
    const int t = threadIdx.x;

    for (int idx = t; idx < 8 * 64; idx += 256) {
        int r = idx >> 6, c = idx & 63;
        size_t off = (size_t)(R0 + r) * CC + c;
        float acc = 0.f;
#pragma unroll
        for (int q = 0; q < 8; q++) acc += g_samp8[q][off];
        s[r * 64 + c] = acc;
    }
    __syncthreads();

    float a1[8];
#pragma unroll
    for (int r = 0; r < 8; r++) a1[r] = b1[t];
#pragma unroll 4
    for (int c = 0; c < CC; c++) {
        float wv = w1[c * PP + t];
#pragma unroll
        for (int r = 0; r < 8; r++) a1[r] += s[r * 64 + c] * wv;
    }
#pragma unroll
    for (int r = 0; r < 8; r++) h[r * 256 + t] = fmaxf(a1[r], 0.f);
    __syncthreads();

    float a2[8];
#pragma unroll
    for (int r = 0; r < 8; r++) a2[r] = b2[t];
#pragma unroll 4
    for (int p2 = 0; p2 < PP; p2++) {
        float wv = w2[p2 * PP + t];
#pragma unroll
        for (int r = 0; r < 8; r++) a2[r] += h[r * 256 + p2] * wv;
    }

    for (int r = 0; r < 8; r++) {
        red[t] = a2[r] * a2[r];
        __syncthreads();
        for (int sd = 128; sd > 0; sd >>= 1) { if (t < sd) red[t] += red[t + sd]; __syncthreads(); }
        float denom = fmaxf(sqrtf(red[0]), 1e-12f);
        __syncthreads();
        emb[(size_t)(R0 + r) * PP + t] = a2[r] / denom;
    }
}

// ---------------------------------------------------------------------------
extern "C" void kernel_launch(void* const* d_in, const int* in_sizes, int n_in,
                              void* d_out, int out_size) {
    const float* L  = (const float*)d_in[0];
    const float* w1 = (const float*)d_in[1];
    const float* b1 = (const float*)d_in[2];
    const float* w2 = (const float*)d_in[3];
    const float* b2 = (const float*)d_in[4];

    float* out  = (float*)d_out;
    float* emb  = out;                                   // [B,K,P]
    float* attn = out + (size_t)BB * KK * PP;            // [B,K,N]
    float* oidx = attn + (size_t)BB * KK * NN;           // [B,K]

    diag_kernel<<<dim3(4, BB), 1024>>>(L);
    entropy_kernel<<<dim3(NPAIRS, BB), 256>>>(L);
    sort_kernel<<<BB, 1024>>>(oidx);
    scores_kernel<<<dim3(16, 4, BB), 256>>>(L, attn);
    sampled_kernel<<<dim3(8, 8, BB), 256>>>(L, attn);
    mlp_kernel<<<128, 256>>>(w1, b1, w2, b2, emb);
}

// round 9
// speedup vs baseline: 3.2947x; 1.1318x over previous
#include <cuda_runtime.h>
#include <math.h>
#include <stdint.h>

#define BB 4
#define CC 64
#define NN 4096
#define KK 256
#define PP 256
#define NTILE 32            // 4096 / 128
#define NPAIRS 528          // 32*33/2 upper-triangle tiles

// Scratch (no allocs allowed) ------------------------------------------------
__device__ float g_diag[BB][NN];            // o_i = ||x_i||^2
__device__ float g_pz[BB][NTILE][NN];       // partial Z (additive, by slot)
__device__ float g_pt[BB][NTILE][NN];       // partial T = sum (s-o)e^(s-o)
__device__ float g_iZ[BB][NN];              // 1/Z per row (from sort pass)
__device__ int   g_sel[BB * KK];            // selected row indices (sorted)
__device__ float g_samp16[16][BB * KK * CC];// j-sixteenth partials of sampled

// ---------------------------------------------------------------------------
// Pass 0: diagonal o_i = sum_c x^2. grid (4, BB), 1024 threads.
// ---------------------------------------------------------------------------
__global__ void diag_kernel(const float* __restrict__ L) {
    const int b = blockIdx.y;
    const int i = blockIdx.x * 1024 + threadIdx.x;
    const float* Lb = L + (size_t)b * CC * NN;
    float acc = 0.f;
#pragma unroll 8
    for (int c = 0; c < CC; c++) {
        float v = Lb[(size_t)c * NN + i];
        acc += v * v;
    }
    g_diag[b][i] = acc;
}

// ---------------------------------------------------------------------------
// Pass 1: symmetric-tile softmax stats with fixed diag offsets (additive).
// One block per (it<=jt) 128x128 tile. grid (528, BB), 256 threads.
// Row (Z,T) -> slot jt; col (transpose) (Z,T) -> slot it (skipped on diagonal).
// ---------------------------------------------------------------------------
__global__ void __launch_bounds__(256, 3)
entropy_kernel(const float* __restrict__ L) {
    __shared__ __align__(16) float Xi[64 * 128];  // 32 KB [c][ii]
    __shared__ __align__(16) float Xj[64 * 64];   // 16 KB [c][jj] + scratch

    // decode upper-triangle pair
    int rem = blockIdx.x, it = 0;
    while (rem >= NTILE - it) { rem -= NTILE - it; it++; }
    const int jt = it + rem;

    const int b = blockIdx.y;
    const int t = threadIdx.x;
    const int tx = t & 15, ty = t >> 4;
    const int i0 = it * 128, j0 = jt * 128;
    const float* Lb = L + (size_t)b * CC * NN;
    const bool offdiag = (it != jt);

    for (int idx = t; idx < 2048; idx += 256) {          // 64*128 floats /4
        int c = idx >> 5, q = idx & 31;
        ((float4*)Xi)[c * 32 + q] = ((const float4*)(Lb + (size_t)c * NN + i0))[q];
    }

    float oi[8];
    {
        float4 o0 = *(const float4*)&g_diag[b][i0 + ty * 8];
        float4 o1 = *(const float4*)&g_diag[b][i0 + ty * 8 + 4];
        oi[0] = o0.x; oi[1] = o0.y; oi[2] = o0.z; oi[3] = o0.w;
        oi[4] = o1.x; oi[5] = o1.y; oi[6] = o1.z; oi[7] = o1.w;
    }

    float z[8], tq[8];
#pragma unroll
    for (int u = 0; u < 8; u++) { z[u] = 0.f; tq[u] = 0.f; }

    for (int h = 0; h < 2; h++) {
        __syncthreads();
        for (int idx = t; idx < 1024; idx += 256) {      // 64*64 /4
            int c = idx >> 4, q = idx & 15;
            ((float4*)Xj)[c * 16 + q] =
                ((const float4*)(Lb + (size_t)c * NN + j0 + h * 64))[q];
        }
        __syncthreads();

        float acc[8][4];
#pragma unroll
        for (int u = 0; u < 8; u++)
#pragma unroll
            for (int v = 0; v < 4; v++) acc[u][v] = 0.f;

#pragma unroll 8
        for (int c = 0; c < 64; c++) {
            float4 a0 = *(const float4*)&Xi[c * 128 + ty * 8];
            float4 a1 = *(const float4*)&Xi[c * 128 + ty * 8 + 4];
            float4 bv = *(const float4*)&Xj[c * 64 + tx * 4];
            float a[8] = {a0.x, a0.y, a0.z, a0.w, a1.x, a1.y, a1.z, a1.w};
            float bb[4] = {bv.x, bv.y, bv.z, bv.w};
#pragma unroll
            for (int u = 0; u < 8; u++)
#pragma unroll
                for (int v = 0; v < 4; v++) acc[u][v] += a[u] * bb[v];
        }

        // row side: additive (Z, T) with fixed offset oi[u]
#pragma unroll
        for (int u = 0; u < 8; u++)
#pragma unroll
            for (int v = 0; v < 4; v++) {
                float s = acc[u][v] - oi[u];
                float e = __expf(s);
                z[u] += e; tq[u] += s * e;
            }

        // col (transpose) side: offsets o_j, reduce over u then over ty
        if (offdiag) {
            float4 ojv = *(const float4*)&g_diag[b][j0 + h * 64 + tx * 4];
            float oj[4] = {ojv.x, ojv.y, ojv.z, ojv.w};
            __syncthreads();                 // done reading Xj; reuse as scratch
            float* scz = Xj;                 // [16][64]
            float* sct = Xj + 1024;
#pragma unroll
            for (int v = 0; v < 4; v++) {
                float zc = 0.f, tc = 0.f;
#pragma unroll
                for (int u = 0; u < 8; u++) {
                    float s = acc[u][v] - oj[v];
                    float e = __expf(s);
                    zc += e; tc += s * e;
                }
                int cl = tx * 4 + v;
                scz[ty * 64 + cl] = zc; sct[ty * 64 + cl] = tc;
            }
            __syncthreads();
            if (t < 64) {
                float Z = 0.f, T = 0.f;
#pragma unroll 4
                for (int g = 0; g < 16; g++) {
                    Z += scz[g * 64 + t];
                    T += sct[g * 64 + t];
                }
                int row = j0 + h * 64 + t;
                g_pz[b][it][row] = Z; g_pt[b][it][row] = T;
            }
        }
    }

    // row merge across tx: plain shuffle adds over 16 lanes, write slot jt
#pragma unroll
    for (int u = 0; u < 8; u++) {
        float Z = z[u], T = tq[u];
#pragma unroll
        for (int d = 8; d >= 1; d >>= 1) {
            Z += __shfl_xor_sync(0xffffffff, Z, d);
            T += __shfl_xor_sync(0xffffffff, T, d);
        }
        if (tx == 0) {
            int row = i0 + ty * 8 + u;
            g_pz[b][jt][row] = Z; g_pt[b][jt][row] = T;
        }
    }
}

// ---------------------------------------------------------------------------
// Pass 2: sum 32 slot-partials -> entropy + 1/Z, then per-batch bitonic
// argsort on packed u64 (orderable float bits << 32 | idx) == stable argsort.
// 4 blocks x 1024 threads.
// ---------------------------------------------------------------------------
__global__ void sort_kernel(float* __restrict__ out_idx) {
    __shared__ unsigned long long kv[NN];
    const int b = blockIdx.x, t = threadIdx.x;
    for (int i = t; i < NN; i += 1024) {
        float Z = 0.f, T = 0.f;
#pragma unroll 8
        for (int s = 0; s < NTILE; s++) {
            Z += g_pz[b][s][i];
            T += g_pt[b][s][i];
        }
        float key = logf(Z) - T / Z;
        g_iZ[b][i] = 1.f / Z;
        unsigned int kb = __float_as_uint(key);
        kb = (kb & 0x80000000u) ? ~kb : (kb | 0x80000000u);
        kv[i] = ((unsigned long long)kb << 32) | (unsigned int)i;
    }
    __syncthreads();
    for (int k = 2; k <= NN; k <<= 1) {
        for (int j = k >> 1; j > 0; j >>= 1) {
            for (int i = t; i < NN; i += 1024) {
                int ixj = i ^ j;
                if (ixj > i) {
                    bool up = ((i & k) == 0);
                    unsigned long long a = kv[i], c = kv[ixj];
                    if ((a > c) == up) { kv[i] = c; kv[ixj] = a; }
                }
            }
            __syncthreads();
        }
    }
    if (t < KK) {
        int v = (int)(kv[t] & 0xffffffffu);
        g_sel[b * KK + t] = v;
        out_idx[b * KK + t] = (float)v;
    }
}

// ---------------------------------------------------------------------------
// Pass 3a: attn = exp(s - o_k) / Z for selected rows (final, normalized).
// grid (4 ktiles, 16 jslabs, B), 256 threads. Block: 64 sel-rows x 256 cols
// (4 inner j-tiles of 64). Thread: 4x4 register tile, LDS.128 both operands.
// ---------------------------------------------------------------------------
__global__ void scores_kernel(const float* __restrict__ L, float* __restrict__ attn) {
    __shared__ __align__(16) float Xi[64 * 64];   // [c][r] 16 KB
    __shared__ __align__(16) float Xj[64 * 64];   // [c][j] 16 KB
    __shared__ float Ob[64], Zb[64];
    const int b  = blockIdx.z;
    const int k0 = blockIdx.x * 64;
    const int jslab = blockIdx.y * 256;
    const int t  = threadIdx.x;
    const int r4 = (t & 15) * 4, c4 = (t >> 4) * 4;
    const float* Lb = L + (size_t)b * CC * NN;

    for (int idx = t; idx < 64 * 64; idx += 256) {
        int c = idx >> 6, rr = idx & 63;
        int col = g_sel[b * KK + k0 + rr];
        Xi[c * 64 + rr] = Lb[(size_t)c * NN + col];
    }
    if (t < 64) {
        int col = g_sel[b * KK + k0 + t];
        Ob[t] = g_diag[b][col];
        Zb[t] = g_iZ[b][col];
    }

    for (int jt = 0; jt < 4; jt++) {
        __syncthreads();
        for (int idx = t; idx < 1024; idx += 256) {   // 64*64 /4 float4s
            int c = idx >> 4, q = idx & 15;
            ((float4*)Xj)[c * 16 + q] =
                ((const float4*)(Lb + (size_t)c * NN + jslab + jt * 64))[q];
        }
        __syncthreads();

        float acc[4][4];
#pragma unroll
        for (int i = 0; i < 4; i++)
#pragma unroll
            for (int j = 0; j < 4; j++) acc[i][j] = 0.f;

#pragma unroll 8
        for (int c = 0; c < 64; c++) {
            float4 a4 = *(const float4*)&Xi[c * 64 + r4];
            float4 b4 = *(const float4*)&Xj[c * 64 + c4];
            float a[4] = {a4.x, a4.y, a4.z, a4.w};
            float bb[4] = {b4.x, b4.y, b4.z, b4.w};
#pragma unroll
            for (int i = 0; i < 4; i++)
#pragma unroll
                for (int j = 0; j < 4; j++) acc[i][j] += a[i] * bb[j];
        }

#pragma unroll
        for (int i = 0; i < 4; i++) {
            float o = Ob[r4 + i], iz = Zb[r4 + i];
            float4 res;
            res.x = __expf(acc[i][0] - o) * iz;
            res.y = __expf(acc[i][1] - o) * iz;
            res.z = __expf(acc[i][2] - o) * iz;
            res.w = __expf(acc[i][3] - o) * iz;
            *(float4*)(attn + ((size_t)b * KK + k0 + r4 + i) * NN
                       + jslab + jt * 64 + c4) = res;
        }
    }
}

// ---------------------------------------------------------------------------
// Pass 3b: partial sampled over one j-sixteenth (256 j) — 64 k x 64 c tiles.
// grid (4 ktiles, 16 jo, B), 256 threads. attn staged transposed so both
// operands load as LDS.128. Thread: 4x4 register tile.
// ---------------------------------------------------------------------------
__global__ void sampled_kernel(const float* __restrict__ L, const float* __restrict__ attn) {
    __shared__ __align__(16) float XT[64 * 68];   // [jj][c], pad 68
    __shared__ __align__(16) float PtT[64 * 68];  // [jj][k], pad 68
    const int b  = blockIdx.z;
    const int k0 = blockIdx.x * 64;
    const int jbase = blockIdx.y * 256;
    const int t  = threadIdx.x;
    const int k4 = (t & 15) * 4, c4 = (t >> 4) * 4;
    const float* Lb = L + (size_t)b * CC * NN;

    float acc[4][4];
#pragma unroll
    for (int i = 0; i < 4; i++)
#pragma unroll
        for (int j = 0; j < 4; j++) acc[i][j] = 0.f;

    for (int jst = 0; jst < 4; jst++) {
        __syncthreads();
        for (int idx = t; idx < 64 * 64; idx += 256) {
            int c = idx >> 6, jj = idx & 63;
            XT[jj * 68 + c] = Lb[(size_t)c * NN + jbase + jst * 64 + jj];
        }
        for (int idx = t; idx < 64 * 64; idx += 256) {
            int kk = idx >> 6, jj = idx & 63;
            PtT[jj * 68 + kk] =
                attn[((size_t)b * KK + k0 + kk) * NN + jbase + jst * 64 + jj];
        }
        __syncthreads();
#pragma unroll 8
        for (int jj = 0; jj < 64; jj++) {
            float4 p4 = *(const float4*)&PtT[jj * 68 + k4];
            float4 x4 = *(const float4*)&XT[jj * 68 + c4];
            float p[4] = {p4.x, p4.y, p4.z, p4.w};
            float x[4] = {x4.x, x4.y, x4.z, x4.w};
#pragma unroll
            for (int i = 0; i < 4; i++)
#pragma unroll
                for (int j = 0; j < 4; j++) acc[i][j] += p[i] * x[j];
        }
    }
    int q = blockIdx.y;
#pragma unroll
    for (int i = 0; i < 4; i++)
        *(float4*)&g_samp16[q][((size_t)b * KK + k0 + k4 + i) * CC + c4] =
            make_float4(acc[i][0], acc[i][1], acc[i][2], acc[i][3]);
}

// ---------------------------------------------------------------------------
// Pass 4: MLP + L2 normalize, 8 rows per block. 128 blocks x 256 threads.
// ---------------------------------------------------------------------------
__global__ void mlp_kernel(const float* __restrict__ w1, const float* __restrict__ b1,
                           const float* __restrict__ w2, const float* __restrict__ b2,
                           float* __restrict__ emb) {
    __shared__ float s[8 * 64];
    __shared__ float h[8 * 256];
    __shared__ float red[256];
    const int R0 = blockIdx.x * 8;
    const int t = threadIdx.x;

    for (int idx = t; idx < 8 * 64; idx += 256) {
        int r = idx >> 6, c = idx & 63;
        size_t off = (size_t)(R0 + r) * CC + c;
        float acc = 0.f;
#pragma unroll
        for (int q = 0; q < 16; q++) acc += g_samp16[q][off];
        s[r * 64 + c] = acc;
    }
    __syncthreads();

    float a1[8];
#pragma unroll
    for (int r = 0; r < 8; r++) a1[r] = b1[t];
#pragma unroll 4
    for (int c = 0; c < CC; c++) {
        float wv = w1[c * PP + t];
#pragma unroll
        for (int r = 0; r < 8; r++) a1[r] += s[r * 64 + c] * wv;
    }
#pragma unroll
    for (int r = 0; r < 8; r++) h[r * 256 + t] = fmaxf(a1[r], 0.f);
    __syncthreads();

    float a2[8];
#pragma unroll
    for (int r = 0; r < 8; r++) a2[r] = b2[t];
#pragma unroll 4
    for (int p2 = 0; p2 < PP; p2++) {
        float wv = w2[p2 * PP + t];
#pragma unroll
        for (int r = 0; r < 8; r++) a2[r] += h[r * 256 + p2] * wv;
    }

    for (int r = 0; r < 8; r++) {
        red[t] = a2[r] * a2[r];
        __syncthreads();
        for (int sd = 128; sd > 0; sd >>= 1) { if (t < sd) red[t] += red[t + sd]; __syncthreads(); }
        float denom = fmaxf(sqrtf(red[0]), 1e-12f);
        __syncthreads();
        emb[(size_t)(R0 + r) * PP + t] = a2[r] / denom;
    }
}

// ---------------------------------------------------------------------------
extern "C" void kernel_launch(void* const* d_in, const int* in_sizes, int n_in,
                              void* d_out, int out_size) {
    const float* L  = (const float*)d_in[0];
    const float* w1 = (const float*)d_in[1];
    const float* b1 = (const float*)d_in[2];
    const float* w2 = (const float*)d_in[3];
    const float* b2 = (const float*)d_in[4];

    float* out  = (float*)d_out;
    float* emb  = out;                                   // [B,K,P]
    float* attn = out + (size_t)BB * KK * PP;            // [B,K,N]
    float* oidx = attn + (size_t)BB * KK * NN;           // [B,K]

    diag_kernel<<<dim3(4, BB), 1024>>>(L);
    entropy_kernel<<<dim3(NPAIRS, BB), 256>>>(L);
    sort_kernel<<<BB, 1024>>>(oidx);
    scores_kernel<<<dim3(4, 16, BB), 256>>>(L, attn);
    sampled_kernel<<<dim3(4, 16, BB), 256>>>(L, attn);
    mlp_kernel<<<128, 256>>>(w1, b1, w2, b2, emb);
}